// round 13
// baseline (speedup 1.0000x reference)
#include <cuda_runtime.h>
#include <cstdint>

// path[row][t] = 0.3 + (lam0[row] - 0.3) * 0.5^t   (closed form of the scan;
// clamp inactive after step 0; 0.5^t exact power of two via exponent bits).
//
// R13: single change vs R10/R12 (best, 23.04us): STG.128 x8 -> 256-bit
// st.global.cs.v8.f32 x4 (sm_100+/PTX 8.8). Same bytes, same 128 B/thread,
// same grid geometry (4096x256, CTAs/SM unchanged -- avoids the R11 cliff),
// but HALF the store instructions -> half the L1tex wavefront-queue
// insertions. Motivated by L1=61.5% being the top pipe on a pure store
// stream. Store policy .cs kept (wb 25.06 / cs 23.04 / wt 26.21 measured).

static constexpr int HORIZON = 256;
static constexpr int T8_PER_ROW = HORIZON / 8;       // 32 float8 per row
static constexpr unsigned GRID = 4096;
static constexpr unsigned BLOCK = 256;
static constexpr unsigned STRIDE = GRID * BLOCK;     // 2^20, multiple of 32
static constexpr unsigned N8 = 131072u * T8_PER_ROW; // 2^22 float8 total
static constexpr int ITERS = N8 / STRIDE;            // exactly 4

__device__ __forceinline__ void st_cs_v8(float* p,
    float a, float b, float c, float d, float e, float f, float g, float h)
{
    asm volatile(
        "st.global.cs.v8.f32 [%0], {%1,%2,%3,%4,%5,%6,%7,%8};"
        :: "l"(p), "f"(a), "f"(b), "f"(c), "f"(d),
           "f"(e), "f"(f), "f"(g), "f"(h)
        : "memory");
}

__global__ __launch_bounds__(BLOCK) void lyap_path_kernel(
    const float* __restrict__ lam0, float* __restrict__ out)
{
    unsigned idx8 = blockIdx.x * BLOCK + threadIdx.x;

    // Loop-invariant: t = 8 * (idx8 % 32) is fixed per thread (STRIDE % 32 == 0).
    int t = (int)(idx8 & (T8_PER_ROW - 1)) << 3;
    int e = 127 - t;
    const float f0 = (e > 0) ? __uint_as_float((unsigned)e << 23) : 0.0f;
    const float f1 = f0 * 0.5f;
    const float f2 = f1 * 0.5f;
    const float f3 = f2 * 0.5f;
    const float f4 = f3 * 0.5f;
    const float f5 = f4 * 0.5f;
    const float f6 = f5 * 0.5f;
    const float f7 = f6 * 0.5f;

    const unsigned row_stride = STRIDE / T8_PER_ROW;  // 32768
    unsigned row = idx8 >> 5;

    #pragma unroll
    for (int i = 0; i < ITERS; i++, idx8 += STRIDE, row += row_stride) {
        float diff = __ldg(&lam0[row]) - 0.3f;

        st_cs_v8(out + (size_t)idx8 * 8,
                 fmaf(diff, f0, 0.3f), fmaf(diff, f1, 0.3f),
                 fmaf(diff, f2, 0.3f), fmaf(diff, f3, 0.3f),
                 fmaf(diff, f4, 0.3f), fmaf(diff, f5, 0.3f),
                 fmaf(diff, f6, 0.3f), fmaf(diff, f7, 0.3f));
    }
}

extern "C" void kernel_launch(void* const* d_in, const int* in_sizes, int n_in,
                              void* d_out, int out_size)
{
    const float* lam0 = (const float*)d_in[0];
    float* out = (float*)d_out;

    lyap_path_kernel<<<GRID, BLOCK>>>(lam0, out);
}